// round 9
// baseline (speedup 1.0000x reference)
#include <cuda_runtime.h>
#include <cuda_fp16.h>
#include <math.h>
#include <stdint.h>

// Problem constants
#define RC_    4        // R*CH
#define NN_    20000
#define EE_    100000
#define CC_    256
#define MTOT_  80000    // R*CH*N

// ---------------------------------------------------------------------------
// Scratch (static device globals; no runtime allocation)
// ---------------------------------------------------------------------------
__device__ __align__(256) float g_xl[MTOT_ * CC_];     // x @ lin_W + lin_b
__device__ int g_is64;

// CSR scratch
__device__ __align__(256) int g_icnt[NN_];             // zero-init; reset by scan
__device__ __align__(256) int g_rowstart[NN_ + 1];
__device__ __align__(256) int g_pos[NN_];
__device__ __align__(256) int g_ebkt[EE_];

// fp16 2-term split operands
__device__ __align__(256) __half g_xhi[MTOT_ * CC_];
__device__ __align__(256) __half g_xlo[MTOT_ * CC_];
__device__ __align__(256) __half g_ahi[MTOT_ * CC_];
__device__ __align__(256) __half g_alo[MTOT_ * CC_];
// Transposed fp16 weights, [n][k] layout
__device__ __align__(256) __half g_WT0[CC_ * CC_];  // lin_W
__device__ __align__(256) __half g_WT2[CC_ * CC_];  // linl_W
__device__ __align__(256) __half g_WT4[CC_ * CC_];  // linr_W

// ---------------------------------------------------------------------------
// PTX helpers (sm_80+ only)
// ---------------------------------------------------------------------------
__device__ __forceinline__ uint32_t smem_u32(const void* p) {
    uint32_t a;
    asm("{ .reg .u64 t; cvta.to.shared.u64 t, %1; cvt.u32.u64 %0, t; }"
        : "=r"(a) : "l"(p));
    return a;
}
__device__ __forceinline__ void cp16(uint32_t saddr, const void* g) {
    asm volatile("cp.async.cg.shared.global [%0], [%1], 16;"
                 :: "r"(saddr), "l"(g) : "memory");
}
#define CP_COMMIT() asm volatile("cp.async.commit_group;" ::: "memory")
#define CP_WAIT1()  asm volatile("cp.async.wait_group 1;" ::: "memory")
#define CP_WAIT0()  asm volatile("cp.async.wait_group 0;" ::: "memory")

#define LDSM4(r, addr) \
    asm volatile("ldmatrix.sync.aligned.m8n8.x4.shared.b16 {%0,%1,%2,%3}, [%4];" \
                 : "=r"((r)[0]), "=r"((r)[1]), "=r"((r)[2]), "=r"((r)[3]) \
                 : "r"(addr))

#define MMA16816(d, a, b0, b1) \
    asm volatile("mma.sync.aligned.m16n8k16.row.col.f32.f16.f16.f32 " \
                 "{%0,%1,%2,%3}, {%4,%5,%6,%7}, {%8,%9}, {%0,%1,%2,%3};" \
                 : "+f"((d)[0]), "+f"((d)[1]), "+f"((d)[2]), "+f"((d)[3]) \
                 : "r"((a)[0]), "r"((a)[1]), "r"((a)[2]), "r"((a)[3]), \
                   "r"(b0), "r"(b1))

// SMEM geometry: padded 80B row stride -> conflict-free ldmatrix
#define ROWB         80
#define TILE_A_BYTES 10240       // 128 rows * 80B
#define TILE_B_BYTES 20480       // 256 rows * 80B
#define STAGE_BYTES  30720       // A tile + B tile
#define NSTAGE       3
#define SMEM_BYTES   92160       // 3 stages

// ---------------------------------------------------------------------------
// edge_index dtype detect + index load
// ---------------------------------------------------------------------------
__global__ void detect_kernel(const int* __restrict__ ei32) {
    __shared__ int any_nonzero;
    if (threadIdx.x == 0) any_nonzero = 0;
    __syncthreads();
    if (ei32[2 * threadIdx.x + 1] != 0) atomicOr(&any_nonzero, 1);
    __syncthreads();
    if (threadIdx.x == 0) g_is64 = (any_nonzero == 0) ? 1 : 0;
}
__device__ __forceinline__ int load_idx(const int* ei32, int pos) {
    int v = g_is64 ? ei32[2 * pos] : ei32[pos];
    return min(max(v, 0), NN_ - 1);
}

// ---------------------------------------------------------------------------
// CSR build: histogram -> scan (+ reset histogram) -> bucket fill
// ---------------------------------------------------------------------------
__global__ void icount_kernel(const int* __restrict__ ei32) {
    int e = blockIdx.x * 256 + threadIdx.x;
    if (e < EE_) atomicAdd(&g_icnt[load_idx(ei32, EE_ + e)], 1);
}

__global__ __launch_bounds__(1024) void scan_kernel() {
    __shared__ int buf[1024];
    __shared__ int carry;
    const int tid = threadIdx.x;
    if (tid == 0) carry = 0;
    __syncthreads();
    for (int chunk = 0; chunk < (NN_ + 1023) / 1024; chunk++) {
        int i = chunk * 1024 + tid;
        int v = (i < NN_) ? g_icnt[i] : 0;
        if (i < NN_) g_icnt[i] = 0;          // reset for next graph replay
        int add = carry;
        buf[tid] = v;
        __syncthreads();
        for (int off = 1; off < 1024; off <<= 1) {
            int t = (tid >= off) ? buf[tid - off] : 0;
            __syncthreads();
            buf[tid] += t;
            __syncthreads();
        }
        if (i < NN_) {
            int excl = add + buf[tid] - v;
            g_rowstart[i] = excl;
            g_pos[i] = excl;
        }
        __syncthreads();
        if (tid == 0) carry = add + buf[1023];
        __syncthreads();
    }
    if (tid == 0) g_rowstart[NN_] = carry;   // == EE_
}

__global__ void fill_kernel(const int* __restrict__ ei32) {
    int e = blockIdx.x * 256 + threadIdx.x;
    if (e < EE_) {
        int dst = load_idx(ei32, EE_ + e);
        int p = atomicAdd(&g_pos[dst], 1);
        g_ebkt[p] = e;
    }
}

// ---------------------------------------------------------------------------
// fp32 -> (hi,lo) fp16 split
// ---------------------------------------------------------------------------
__device__ __forceinline__ void split4(float4 v, __half2* H, __half2* L, size_t i4) {
    __half h0 = __float2half_rn(v.x);
    __half h1 = __float2half_rn(v.y);
    __half h2 = __float2half_rn(v.z);
    __half h3 = __float2half_rn(v.w);
    __half2 p;
    p.x = h0; p.y = h1; H[i4 * 2 + 0] = p;
    p.x = h2; p.y = h3; H[i4 * 2 + 1] = p;
    p.x = __float2half_rn(v.x - __half2float(h0));
    p.y = __float2half_rn(v.y - __half2float(h1));
    L[i4 * 2 + 0] = p;
    p.x = __float2half_rn(v.z - __half2float(h2));
    p.y = __float2half_rn(v.w - __half2float(h3));
    L[i4 * 2 + 1] = p;
}

__global__ void xsplit_kernel(const float* __restrict__ x) {
    size_t i4 = (size_t)blockIdx.x * 256 + threadIdx.x;
    float4 v = ((const float4*)x)[i4];
    split4(v, (__half2*)g_xhi, (__half2*)g_xlo, i4);
}

__global__ void wprep_kernel(const float* __restrict__ W0,
                             const float* __restrict__ W1,
                             const float* __restrict__ W2) {
    const float* W = (blockIdx.y == 0) ? W0 : ((blockIdx.y == 1) ? W1 : W2);
    __half* H = (blockIdx.y == 0) ? g_WT0 : ((blockIdx.y == 1) ? g_WT2 : g_WT4);
    int k = blockIdx.x, n = threadIdx.x;
    H[n * CC_ + k] = __float2half_rn(W[k * CC_ + n]);
}

// ---------------------------------------------------------------------------
// Fused message gather: block = dst node, thread = channel.
// ---------------------------------------------------------------------------
__global__ __launch_bounds__(256) void gather_kernel(
    const float* __restrict__ edge_attr,    // (E,16)
    const float* __restrict__ bond_W,       // (16,256)
    const float* __restrict__ bond_b,       // (256)
    const float* __restrict__ edge_weight,  // (RC, E)
    const int* __restrict__ ei32)
{
    const int n = blockIdx.x;
    const int c = threadIdx.x;

    float bw[16];
#pragma unroll
    for (int d = 0; d < 16; d++) bw[d] = bond_W[d * CC_ + c];
    const float bb = bond_b[c];

    const int s0 = g_rowstart[n];
    const int s1 = g_rowstart[n + 1];
    const int deg = s1 - s0;

    float acc0 = 0.f, acc1 = 0.f, acc2 = 0.f, acc3 = 0.f;

    for (int i = s0; i < s1; i++) {
        const int e = g_ebkt[i];
        const int src = load_idx(ei32, e);

        float emb = bb;
#pragma unroll
        for (int d = 0; d < 16; d++)
            emb = fmaf(__ldg(&edge_attr[e * 16 + d]), bw[d], emb);

        const float w0 = __ldg(&edge_weight[0 * EE_ + e]);
        const float w1 = __ldg(&edge_weight[1 * EE_ + e]);
        const float w2 = __ldg(&edge_weight[2 * EE_ + e]);
        const float w3 = __ldg(&edge_weight[3 * EE_ + e]);

        const float* xr = g_xl + (size_t)src * CC_ + c;
        const size_t rs = (size_t)NN_ * CC_;
        float v0 = xr[0 * rs] + emb;
        float v1 = xr[1 * rs] + emb;
        float v2 = xr[2 * rs] + emb;
        float v3 = xr[3 * rs] + emb;
        const float k = 0.70710678118654752f;
        acc0 += 0.5f * v0 * (1.0f + erff(v0 * k)) * w0;
        acc1 += 0.5f * v1 * (1.0f + erff(v1 * k)) * w1;
        acc2 += 0.5f * v2 * (1.0f + erff(v2 * k)) * w2;
        acc3 += 0.5f * v3 * (1.0f + erff(v3 * k)) * w3;
    }

    const float s = 1.0f / (float)max(deg, 1);
    float a[4] = {acc0 * s, acc1 * s, acc2 * s, acc3 * s};
#pragma unroll
    for (int rc = 0; rc < RC_; rc++) {
        size_t off = (size_t)(rc * NN_ + n) * CC_ + c;
        __half h = __float2half_rn(a[rc]);
        g_ahi[off] = h;
        g_alo[off] = __float2half_rn(a[rc] - __half2float(h));
    }
}

// ---------------------------------------------------------------------------
// fp16 mma.sync GEMM, 3-stage cp.async pipeline.
// CTA tile 128x256 (full N), 8 warps (2M x 4N), warp tile 64x64.
// which==0: g_xl = [xhi,xlo] @ [W0,W0]^T + lin_b                 (K=512)
// which==1: out  = [ahi,alo,xhi,xlo] @ [W2,W2,W4,W4]^T + linl_b  (K=1024)
// ---------------------------------------------------------------------------
__device__ __forceinline__ void load_stage(char* smem, int s, int tid,
                                           const __half* Ag, const __half* Bg) {
    uint32_t a32 = smem_u32(smem + s * STAGE_BYTES);
    uint32_t b32 = a32 + TILE_A_BYTES;
#pragma unroll
    for (int i = 0; i < 2; i++) {                 // A: 128 rows x 64B
        int idx = tid + i * 256;                  // 0..511
        int r = idx >> 2, ch = idx & 3;
        cp16(a32 + r * ROWB + ch * 16,
             (const char*)Ag + ((size_t)r * CC_ + ch * 8) * 2);
    }
#pragma unroll
    for (int i = 0; i < 4; i++) {                 // B: 256 rows x 64B
        int idx = tid + i * 256;                  // 0..1023
        int r = idx >> 2, ch = idx & 3;
        cp16(b32 + r * ROWB + ch * 16,
             (const char*)Bg + ((size_t)r * CC_ + ch * 8) * 2);
    }
}

__global__ __launch_bounds__(256, 1) void mma_gemm(
    int which, const float* __restrict__ bias, float* __restrict__ out_ext)
{
    extern __shared__ __align__(128) char smem[];
    const int tid = threadIdx.x, lane = tid & 31, wid = tid >> 5;
    const int warp_m = wid & 1, warp_n = wid >> 1;
    const int by = blockIdx.x;
    const int g = lane >> 3, lr = lane & 7;

    const __half *Aseg[4], *Bseg[4];
    int nseg;
    float* outp;
    if (which == 0) {
        Aseg[0] = g_xhi; Aseg[1] = g_xlo;
        Bseg[0] = g_WT0; Bseg[1] = g_WT0;
        nseg = 2; outp = g_xl;
    } else {
        Aseg[0] = g_ahi; Aseg[1] = g_alo; Aseg[2] = g_xhi; Aseg[3] = g_xlo;
        Bseg[0] = g_WT2; Bseg[1] = g_WT2; Bseg[2] = g_WT4; Bseg[3] = g_WT4;
        nseg = 4; outp = out_ext;
    }
    const int NC = nseg * 8;    // BK=32 chunks per 256-K segment

    float acc[4][8][4];
#pragma unroll
    for (int mt = 0; mt < 4; mt++)
#pragma unroll
        for (int nt = 0; nt < 8; nt++)
#pragma unroll
            for (int q = 0; q < 4; q++) acc[mt][nt][q] = 0.f;

    const size_t arow = (size_t)by * 128 * CC_;

    // Prologue: load chunks 0 and 1
    load_stage(smem, 0, tid, Aseg[0] + arow, Bseg[0]);
    CP_COMMIT();
    {
        int seg = 1 >> 3, ko = (1 & 7) * 32;
        load_stage(smem, 1, tid, Aseg[seg] + arow + ko, Bseg[seg] + ko);
        CP_COMMIT();
    }

    int buf = 0;
    for (int c = 0; c < NC; c++) {
        if (c + 1 < NC) { CP_WAIT1(); } else { CP_WAIT0(); }
        __syncthreads();

        if (c + 2 < NC) {
            int seg = (c + 2) >> 3, ko = ((c + 2) & 7) * 32;
            int nb = (buf + 2 >= NSTAGE) ? buf + 2 - NSTAGE : buf + 2;
            load_stage(smem, nb, tid, Aseg[seg] + arow + ko, Bseg[seg] + ko);
            CP_COMMIT();
        }

        uint32_t a_base = smem_u32(smem + buf * STAGE_BYTES);
        uint32_t b_base = a_base + TILE_A_BYTES;
#pragma unroll
        for (int ks = 0; ks < 2; ks++) {
            uint32_t a[4][4];
#pragma unroll
            for (int mt = 0; mt < 4; mt++) {
                int row = warp_m * 64 + mt * 16 + (g & 1) * 8 + lr;
                LDSM4(a[mt], a_base + row * ROWB + ks * 32 + (g >> 1) * 16);
            }
            uint32_t b[4][4];
#pragma unroll
            for (int p = 0; p < 4; p++) {
                int row = warp_n * 64 + p * 16 + ((g >> 1) & 1) * 8 + lr;
                LDSM4(b[p], b_base + row * ROWB + ks * 32 + (g & 1) * 16);
            }
#pragma unroll
            for (int mt = 0; mt < 4; mt++)
#pragma unroll
                for (int nt = 0; nt < 8; nt++) {
                    int p = nt >> 1, h = (nt & 1) * 2;
                    MMA16816(acc[mt][nt], a[mt], b[p][h], b[p][h + 1]);
                }
        }
        buf = (buf + 1 >= NSTAGE) ? 0 : buf + 1;
    }

    const int tg = lane >> 2, tig = lane & 3;
#pragma unroll
    for (int mt = 0; mt < 4; mt++) {
#pragma unroll
        for (int nt = 0; nt < 8; nt++) {
            int row = by * 128 + warp_m * 64 + mt * 16 + tg;
            int col = warp_n * 64 + nt * 8 + tig * 2;
            float b0 = bias[col], b1 = bias[col + 1];
            float2 v0, v1;
            v0.x = acc[mt][nt][0] + b0; v0.y = acc[mt][nt][1] + b1;
            v1.x = acc[mt][nt][2] + b0; v1.y = acc[mt][nt][3] + b1;
            *(float2*)(outp + (size_t)row * CC_ + col) = v0;
            *(float2*)(outp + (size_t)(row + 8) * CC_ + col) = v1;
        }
    }
}

// ---------------------------------------------------------------------------
extern "C" void kernel_launch(void* const* d_in, const int* in_sizes, int n_in,
                              void* d_out, int out_size) {
    const float* x           = (const float*)d_in[0];
    const float* edge_attr   = (const float*)d_in[1];
    const float* edge_weight = (const float*)d_in[2];
    const float* lin_W       = (const float*)d_in[3];
    const float* lin_b       = (const float*)d_in[4];
    const float* linl_W      = (const float*)d_in[5];
    const float* linl_b      = (const float*)d_in[6];
    const float* linr_W      = (const float*)d_in[7];
    const float* bond_W      = (const float*)d_in[8];
    const float* bond_b      = (const float*)d_in[9];
    const int*   edge_index  = (const int*)d_in[10];
    float*       out         = (float*)d_out;

    cudaFuncSetAttribute(mma_gemm, cudaFuncAttributeMaxDynamicSharedMemorySize,
                         SMEM_BYTES);

    // Order chosen so mma_gemm(0) is the 4th launch (ncu capture slot).
    xsplit_kernel<<<20000, 256>>>(x);
    wprep_kernel<<<dim3(256, 3), 256>>>(lin_W, linl_W, linr_W);
    detect_kernel<<<1, 256>>>(edge_index);
    mma_gemm<<<MTOT_ / 128, 256, SMEM_BYTES>>>(0, lin_b, nullptr);   // -> g_xl
    icount_kernel<<<(EE_ + 255) / 256, 256>>>(edge_index);
    scan_kernel<<<1, 1024>>>();
    fill_kernel<<<(EE_ + 255) / 256, 256>>>(edge_index);
    gather_kernel<<<NN_, 256>>>(edge_attr, bond_W, bond_b, edge_weight, edge_index);
    mma_gemm<<<MTOT_ / 128, 256, SMEM_BYTES>>>(1, linl_b, out);      // -> out
}

// round 12
// speedup vs baseline: 1.2292x; 1.2292x over previous
#include <cuda_runtime.h>
#include <cuda_fp16.h>
#include <math.h>
#include <stdint.h>

// Problem constants
#define RC_    4        // R*CH
#define NN_    20000
#define EE_    100000
#define CC_    256
#define MTOT_  80000    // R*CH*N

// ---------------------------------------------------------------------------
// Scratch (static device globals; no runtime allocation)
// ---------------------------------------------------------------------------
__device__ __align__(256) float g_xl[MTOT_ * CC_];     // x @ lin_W + lin_b
__device__ int g_is64;

// CSR scratch
__device__ __align__(256) int g_icnt[NN_];             // zero-init; reset by scan
__device__ __align__(256) int g_rowstart[NN_ + 1];
__device__ __align__(256) int g_pos[NN_];
__device__ __align__(256) int g_ebkt[EE_];             // edge id per CSR slot
__device__ __align__(256) int g_esrc[EE_];             // src node per CSR slot

// fp16 2-term split operands
__device__ __align__(256) __half g_xhi[MTOT_ * CC_];
__device__ __align__(256) __half g_xlo[MTOT_ * CC_];
__device__ __align__(256) __half g_ahi[MTOT_ * CC_];
__device__ __align__(256) __half g_alo[MTOT_ * CC_];
// Transposed fp16 weights, [n][k] layout
__device__ __align__(256) __half g_WT0[CC_ * CC_];  // lin_W
__device__ __align__(256) __half g_WT2[CC_ * CC_];  // linl_W
__device__ __align__(256) __half g_WT4[CC_ * CC_];  // linr_W

// ---------------------------------------------------------------------------
// PTX helpers (sm_80+ only)
// ---------------------------------------------------------------------------
__device__ __forceinline__ uint32_t smem_u32(const void* p) {
    uint32_t a;
    asm("{ .reg .u64 t; cvta.to.shared.u64 t, %1; cvt.u32.u64 %0, t; }"
        : "=r"(a) : "l"(p));
    return a;
}
__device__ __forceinline__ void cp16(uint32_t saddr, const void* g) {
    asm volatile("cp.async.cg.shared.global [%0], [%1], 16;"
                 :: "r"(saddr), "l"(g) : "memory");
}
#define CP_COMMIT() asm volatile("cp.async.commit_group;" ::: "memory")
#define CP_WAIT1()  asm volatile("cp.async.wait_group 1;" ::: "memory")
#define CP_WAIT0()  asm volatile("cp.async.wait_group 0;" ::: "memory")

#define LDSM4(r, addr) \
    asm volatile("ldmatrix.sync.aligned.m8n8.x4.shared.b16 {%0,%1,%2,%3}, [%4];" \
                 : "=r"((r)[0]), "=r"((r)[1]), "=r"((r)[2]), "=r"((r)[3]) \
                 : "r"(addr))

#define MMA16816(d, a, b0, b1) \
    asm volatile("mma.sync.aligned.m16n8k16.row.col.f32.f16.f16.f32 " \
                 "{%0,%1,%2,%3}, {%4,%5,%6,%7}, {%8,%9}, {%0,%1,%2,%3};" \
                 : "+f"((d)[0]), "+f"((d)[1]), "+f"((d)[2]), "+f"((d)[3]) \
                 : "r"((a)[0]), "r"((a)[1]), "r"((a)[2]), "r"((a)[3]), \
                   "r"(b0), "r"(b1))

// SMEM geometry: padded 80B row stride -> conflict-free ldmatrix
#define ROWB        80
#define TILE_BYTES  10240        // 128 rows * 80B
#define STAGE_BYTES 20480        // A tile + B tile
#define NSTAGE      3
#define SMEM_BYTES  61440        // 3 stages

// ---------------------------------------------------------------------------
// edge_index dtype detect + index load
// ---------------------------------------------------------------------------
__global__ void detect_kernel(const int* __restrict__ ei32) {
    __shared__ int any_nonzero;
    if (threadIdx.x == 0) any_nonzero = 0;
    __syncthreads();
    if (ei32[2 * threadIdx.x + 1] != 0) atomicOr(&any_nonzero, 1);
    __syncthreads();
    if (threadIdx.x == 0) g_is64 = (any_nonzero == 0) ? 1 : 0;
}
__device__ __forceinline__ int load_idx(const int* ei32, int pos) {
    int v = g_is64 ? ei32[2 * pos] : ei32[pos];
    return min(max(v, 0), NN_ - 1);
}

// ---------------------------------------------------------------------------
// CSR build: histogram -> scan (+ reset histogram) -> bucket fill
// ---------------------------------------------------------------------------
__global__ void icount_kernel(const int* __restrict__ ei32) {
    int e = blockIdx.x * 256 + threadIdx.x;
    if (e < EE_) atomicAdd(&g_icnt[load_idx(ei32, EE_ + e)], 1);
}

__global__ __launch_bounds__(1024) void scan_kernel() {
    __shared__ int buf[1024];
    __shared__ int carry;
    const int tid = threadIdx.x;
    if (tid == 0) carry = 0;
    __syncthreads();
    for (int chunk = 0; chunk < (NN_ + 1023) / 1024; chunk++) {
        int i = chunk * 1024 + tid;
        int v = (i < NN_) ? g_icnt[i] : 0;
        if (i < NN_) g_icnt[i] = 0;          // reset for next graph replay
        int add = carry;
        buf[tid] = v;
        __syncthreads();
        for (int off = 1; off < 1024; off <<= 1) {
            int t = (tid >= off) ? buf[tid - off] : 0;
            __syncthreads();
            buf[tid] += t;
            __syncthreads();
        }
        if (i < NN_) {
            int excl = add + buf[tid] - v;
            g_rowstart[i] = excl;
            g_pos[i] = excl;
        }
        __syncthreads();
        if (tid == 0) carry = add + buf[1023];
        __syncthreads();
    }
    if (tid == 0) g_rowstart[NN_] = carry;   // == EE_
}

__global__ void fill_kernel(const int* __restrict__ ei32) {
    int e = blockIdx.x * 256 + threadIdx.x;
    if (e < EE_) {
        int dst = load_idx(ei32, EE_ + e);
        int src = load_idx(ei32, e);
        int p = atomicAdd(&g_pos[dst], 1);
        g_ebkt[p] = e;
        g_esrc[p] = src;
    }
}

// ---------------------------------------------------------------------------
// fp32 -> (hi,lo) fp16 split
// ---------------------------------------------------------------------------
__device__ __forceinline__ void split4(float4 v, __half2* H, __half2* L, size_t i4) {
    __half h0 = __float2half_rn(v.x);
    __half h1 = __float2half_rn(v.y);
    __half h2 = __float2half_rn(v.z);
    __half h3 = __float2half_rn(v.w);
    __half2 p;
    p.x = h0; p.y = h1; H[i4 * 2 + 0] = p;
    p.x = h2; p.y = h3; H[i4 * 2 + 1] = p;
    p.x = __float2half_rn(v.x - __half2float(h0));
    p.y = __float2half_rn(v.y - __half2float(h1));
    L[i4 * 2 + 0] = p;
    p.x = __float2half_rn(v.z - __half2float(h2));
    p.y = __float2half_rn(v.w - __half2float(h3));
    L[i4 * 2 + 1] = p;
}

__global__ void xsplit_kernel(const float* __restrict__ x) {
    size_t i4 = (size_t)blockIdx.x * 256 + threadIdx.x;
    float4 v = ((const float4*)x)[i4];
    split4(v, (__half2*)g_xhi, (__half2*)g_xlo, i4);
}

__global__ void wprep_kernel(const float* __restrict__ W0,
                             const float* __restrict__ W1,
                             const float* __restrict__ W2) {
    const float* W = (blockIdx.y == 0) ? W0 : ((blockIdx.y == 1) ? W1 : W2);
    __half* H = (blockIdx.y == 0) ? g_WT0 : ((blockIdx.y == 1) ? g_WT2 : g_WT4);
    int k = blockIdx.x, n = threadIdx.x;
    H[n * CC_ + k] = __float2half_rn(W[k * CC_ + n]);
}

// ---------------------------------------------------------------------------
// Fused message gather, chunked-MLP version.
// Block = dst node. Per 32-edge chunk: stage eid/src/weights/edge_attr into
// shared (parallel), then per-channel loop issues independent g_xl row loads.
// ---------------------------------------------------------------------------
__global__ __launch_bounds__(256) void gather_kernel(
    const float* __restrict__ edge_attr,    // (E,16)
    const float* __restrict__ bond_W,       // (16,256)
    const float* __restrict__ bond_b,       // (256)
    const float* __restrict__ edge_weight)  // (RC, E)
{
    const int n = blockIdx.x;
    const int c = threadIdx.x;

    __shared__ int   s_eid[32];
    __shared__ int   s_src[32];
    __shared__ float s_w[4][32];
    __shared__ float s_ea[32][16];

    float bw[16];
#pragma unroll
    for (int d = 0; d < 16; d++) bw[d] = bond_W[d * CC_ + c];
    const float bb = bond_b[c];

    const int s0 = g_rowstart[n];
    const int s1 = g_rowstart[n + 1];
    const int deg = s1 - s0;

    float acc0 = 0.f, acc1 = 0.f, acc2 = 0.f, acc3 = 0.f;
    const size_t rs = (size_t)NN_ * CC_;

    for (int base = s0; base < s1; base += 32) {
        const int m = min(32, s1 - base);

        // Phase 1: eid / src / weights
        if (c < m) {
            int e = g_ebkt[base + c];
            s_eid[c] = e;
            s_src[c] = g_esrc[base + c];
            s_w[0][c] = __ldg(&edge_weight[0 * EE_ + e]);
            s_w[1][c] = __ldg(&edge_weight[1 * EE_ + e]);
            s_w[2][c] = __ldg(&edge_weight[2 * EE_ + e]);
            s_w[3][c] = __ldg(&edge_weight[3 * EE_ + e]);
        }
        __syncthreads();

        // Phase 2: edge_attr (m*16 floats, parallel)
        for (int j = c; j < m * 16; j += 256) {
            s_ea[j >> 4][j & 15] = __ldg(&edge_attr[s_eid[j >> 4] * 16 + (j & 15)]);
        }
        __syncthreads();

        // Phase 3: per-channel accumulation; loads independent across i
#pragma unroll 2
        for (int i = 0; i < m; i++) {
            float emb = bb;
#pragma unroll
            for (int d = 0; d < 16; d++) emb = fmaf(s_ea[i][d], bw[d], emb);

            const float* xr = g_xl + (size_t)s_src[i] * CC_ + c;
            float v0 = xr[0 * rs] + emb;
            float v1 = xr[1 * rs] + emb;
            float v2 = xr[2 * rs] + emb;
            float v3 = xr[3 * rs] + emb;
            const float k = 0.70710678118654752f;
            acc0 += 0.5f * v0 * (1.0f + erff(v0 * k)) * s_w[0][i];
            acc1 += 0.5f * v1 * (1.0f + erff(v1 * k)) * s_w[1][i];
            acc2 += 0.5f * v2 * (1.0f + erff(v2 * k)) * s_w[2][i];
            acc3 += 0.5f * v3 * (1.0f + erff(v3 * k)) * s_w[3][i];
        }
        __syncthreads();
    }

    const float s = 1.0f / (float)max(deg, 1);
    float a[4] = {acc0 * s, acc1 * s, acc2 * s, acc3 * s};
#pragma unroll
    for (int rc = 0; rc < RC_; rc++) {
        size_t off = (size_t)(rc * NN_ + n) * CC_ + c;
        __half h = __float2half_rn(a[rc]);
        g_ahi[off] = h;
        g_alo[off] = __float2half_rn(a[rc] - __half2float(h));
    }
}

// ---------------------------------------------------------------------------
// fp16 mma.sync GEMM, 3-stage cp.async pipeline (R8 config: 128x128, 2 CTA/SM).
// 8 warps (2M x 4N), warp tile 64x32.
// which==0: g_xl = [xhi,xlo] @ [W0,W0]^T + lin_b                 (K=512)
// which==1: out  = [ahi,alo,xhi,xlo] @ [W2,W2,W4,W4]^T + linl_b  (K=1024)
// ---------------------------------------------------------------------------
__device__ __forceinline__ void load_stage(char* smem, int s, int tid,
                                           const __half* Ag, const __half* Bg) {
    uint32_t a32 = smem_u32(smem + s * STAGE_BYTES);
    uint32_t b32 = a32 + TILE_BYTES;
#pragma unroll
    for (int i = 0; i < 2; i++) {
        int idx = tid + i * 256;       // 0..511
        int r = idx >> 2, ch = idx & 3;
        cp16(a32 + r * ROWB + ch * 16,
             (const char*)Ag + ((size_t)r * CC_ + ch * 8) * 2);
    }
#pragma unroll
    for (int i = 0; i < 2; i++) {
        int idx = tid + i * 256;
        int r = idx >> 2, ch = idx & 3;
        cp16(b32 + r * ROWB + ch * 16,
             (const char*)Bg + ((size_t)r * CC_ + ch * 8) * 2);
    }
}

__global__ __launch_bounds__(256, 2) void mma_gemm(
    int which, const float* __restrict__ bias, float* __restrict__ out_ext)
{
    extern __shared__ __align__(128) char smem[];
    const int tid = threadIdx.x, lane = tid & 31, wid = tid >> 5;
    const int warp_m = wid & 1, warp_n = wid >> 1;
    const int bx = blockIdx.x, by = blockIdx.y;
    const int g = lane >> 3, lr = lane & 7;

    const __half *Aseg[4], *Bseg[4];
    int nseg;
    float* outp;
    if (which == 0) {
        Aseg[0] = g_xhi; Aseg[1] = g_xlo;
        Bseg[0] = g_WT0; Bseg[1] = g_WT0;
        nseg = 2; outp = g_xl;
    } else {
        Aseg[0] = g_ahi; Aseg[1] = g_alo; Aseg[2] = g_xhi; Aseg[3] = g_xlo;
        Bseg[0] = g_WT2; Bseg[1] = g_WT2; Bseg[2] = g_WT4; Bseg[3] = g_WT4;
        nseg = 4; outp = out_ext;
    }
    const int NC = nseg * 8;    // BK=32 chunks per 256-K segment

    float acc[4][4][4];
#pragma unroll
    for (int mt = 0; mt < 4; mt++)
#pragma unroll
        for (int nt = 0; nt < 4; nt++)
#pragma unroll
            for (int q = 0; q < 4; q++) acc[mt][nt][q] = 0.f;

    const size_t arow = (size_t)by * 128 * CC_;
    const size_t brow = (size_t)bx * 128 * CC_;

    load_stage(smem, 0, tid, Aseg[0] + arow, Bseg[0] + brow);
    CP_COMMIT();
    {
        int seg = 1 >> 3, ko = (1 & 7) * 32;
        load_stage(smem, 1, tid, Aseg[seg] + arow + ko, Bseg[seg] + brow + ko);
        CP_COMMIT();
    }

    int buf = 0;
    for (int c = 0; c < NC; c++) {
        if (c + 1 < NC) { CP_WAIT1(); } else { CP_WAIT0(); }
        __syncthreads();

        if (c + 2 < NC) {
            int seg = (c + 2) >> 3, ko = ((c + 2) & 7) * 32;
            int nb = (buf + 2 >= NSTAGE) ? buf + 2 - NSTAGE : buf + 2;
            load_stage(smem, nb, tid,
                       Aseg[seg] + arow + ko, Bseg[seg] + brow + ko);
            CP_COMMIT();
        }

        uint32_t a_base = smem_u32(smem + buf * STAGE_BYTES);
        uint32_t b_base = a_base + TILE_BYTES;
#pragma unroll
        for (int ks = 0; ks < 2; ks++) {
            uint32_t a[4][4];
#pragma unroll
            for (int mt = 0; mt < 4; mt++) {
                int row = warp_m * 64 + mt * 16 + (g & 1) * 8 + lr;
                LDSM4(a[mt], a_base + row * ROWB + ks * 32 + (g >> 1) * 16);
            }
            uint32_t b[2][4];
#pragma unroll
            for (int p = 0; p < 2; p++) {
                int row = warp_n * 32 + p * 16 + ((g >> 1) & 1) * 8 + lr;
                LDSM4(b[p], b_base + row * ROWB + ks * 32 + (g & 1) * 16);
            }
#pragma unroll
            for (int mt = 0; mt < 4; mt++)
#pragma unroll
                for (int nt = 0; nt < 4; nt++) {
                    int p = nt >> 1, h = (nt & 1) * 2;
                    MMA16816(acc[mt][nt], a[mt], b[p][h], b[p][h + 1]);
                }
        }
        buf = (buf + 1 >= NSTAGE) ? 0 : buf + 1;
    }

    const int tg = lane >> 2, tig = lane & 3;
#pragma unroll
    for (int mt = 0; mt < 4; mt++) {
#pragma unroll
        for (int nt = 0; nt < 4; nt++) {
            int row = by * 128 + warp_m * 64 + mt * 16 + tg;
            int col = bx * 128 + warp_n * 32 + nt * 8 + tig * 2;
            float b0 = bias[col], b1 = bias[col + 1];
            float2 v0, v1;
            v0.x = acc[mt][nt][0] + b0; v0.y = acc[mt][nt][1] + b1;
            v1.x = acc[mt][nt][2] + b0; v1.y = acc[mt][nt][3] + b1;
            *(float2*)(outp + (size_t)row * CC_ + col) = v0;
            *(float2*)(outp + (size_t)(row + 8) * CC_ + col) = v1;
        }
    }
}

// ---------------------------------------------------------------------------
extern "C" void kernel_launch(void* const* d_in, const int* in_sizes, int n_in,
                              void* d_out, int out_size) {
    const float* x           = (const float*)d_in[0];
    const float* edge_attr   = (const float*)d_in[1];
    const float* edge_weight = (const float*)d_in[2];
    const float* lin_W       = (const float*)d_in[3];
    const float* lin_b       = (const float*)d_in[4];
    const float* linl_W      = (const float*)d_in[5];
    const float* linl_b      = (const float*)d_in[6];
    const float* linr_W      = (const float*)d_in[7];
    const float* bond_W      = (const float*)d_in[8];
    const float* bond_b      = (const float*)d_in[9];
    const int*   edge_index  = (const int*)d_in[10];
    float*       out         = (float*)d_out;

    cudaFuncSetAttribute(mma_gemm, cudaFuncAttributeMaxDynamicSharedMemorySize,
                         SMEM_BYTES);

    // mma_gemm(0) in the 4th (profiled) slot.
    xsplit_kernel<<<20000, 256>>>(x);
    wprep_kernel<<<dim3(256, 3), 256>>>(lin_W, linl_W, linr_W);
    detect_kernel<<<1, 256>>>(edge_index);
    {
        dim3 grid(2, MTOT_ / 128);
        mma_gemm<<<grid, 256, SMEM_BYTES>>>(0, lin_b, nullptr);   // -> g_xl
    }
    icount_kernel<<<(EE_ + 255) / 256, 256>>>(edge_index);
    scan_kernel<<<1, 1024>>>();
    fill_kernel<<<(EE_ + 255) / 256, 256>>>(edge_index);
    gather_kernel<<<NN_, 256>>>(edge_attr, bond_W, bond_b, edge_weight);
    {
        dim3 grid(2, MTOT_ / 128);
        mma_gemm<<<grid, 256, SMEM_BYTES>>>(1, linl_b, out);      // -> out
    }
}

// round 13
// speedup vs baseline: 1.5758x; 1.2820x over previous
#include <cuda_runtime.h>
#include <cuda_fp16.h>
#include <math.h>
#include <stdint.h>

// Problem constants
#define RC_    4        // R*CH
#define NN_    20000
#define EE_    100000
#define CC_    256
#define MTOT_  80000    // R*CH*N

// ---------------------------------------------------------------------------
// Scratch (static device globals; no runtime allocation)
// ---------------------------------------------------------------------------
__device__ __align__(256) float g_xl[MTOT_ * CC_];     // x @ lin_W + lin_b
__device__ int g_is64;

// CSR scratch
__device__ __align__(256) int g_icnt[NN_];             // zero-init; reset by scan
__device__ __align__(256) int g_rowstart[NN_ + 1];
__device__ __align__(256) int g_pos[NN_];
__device__ __align__(256) int g_ebkt[EE_];             // edge id per CSR slot
__device__ __align__(256) int g_esrc[EE_];             // src node per CSR slot

// fp16 operands (no splits: weight quantization dominates error anyway)
__device__ __align__(256) __half g_xh[MTOT_ * CC_];
__device__ __align__(256) __half g_ah[MTOT_ * CC_];
// Transposed fp16 weights, [n][k] layout
__device__ __align__(256) __half g_WT0[CC_ * CC_];  // lin_W
__device__ __align__(256) __half g_WT2[CC_ * CC_];  // linl_W
__device__ __align__(256) __half g_WT4[CC_ * CC_];  // linr_W

// ---------------------------------------------------------------------------
// PTX helpers (sm_80+ only)
// ---------------------------------------------------------------------------
__device__ __forceinline__ uint32_t smem_u32(const void* p) {
    uint32_t a;
    asm("{ .reg .u64 t; cvta.to.shared.u64 t, %1; cvt.u32.u64 %0, t; }"
        : "=r"(a) : "l"(p));
    return a;
}
__device__ __forceinline__ void cp16(uint32_t saddr, const void* g) {
    asm volatile("cp.async.cg.shared.global [%0], [%1], 16;"
                 :: "r"(saddr), "l"(g) : "memory");
}
#define CP_COMMIT() asm volatile("cp.async.commit_group;" ::: "memory")
#define CP_WAIT1()  asm volatile("cp.async.wait_group 1;" ::: "memory")
#define CP_WAIT0()  asm volatile("cp.async.wait_group 0;" ::: "memory")

#define LDSM4(r, addr) \
    asm volatile("ldmatrix.sync.aligned.m8n8.x4.shared.b16 {%0,%1,%2,%3}, [%4];" \
                 : "=r"((r)[0]), "=r"((r)[1]), "=r"((r)[2]), "=r"((r)[3]) \
                 : "r"(addr))

#define MMA16816(d, a, b0, b1) \
    asm volatile("mma.sync.aligned.m16n8k16.row.col.f32.f16.f16.f32 " \
                 "{%0,%1,%2,%3}, {%4,%5,%6,%7}, {%8,%9}, {%0,%1,%2,%3};" \
                 : "+f"((d)[0]), "+f"((d)[1]), "+f"((d)[2]), "+f"((d)[3]) \
                 : "r"((a)[0]), "r"((a)[1]), "r"((a)[2]), "r"((a)[3]), \
                   "r"(b0), "r"(b1))

// SMEM geometry: padded 80B row stride -> conflict-free ldmatrix
#define ROWB        80
#define TILE_BYTES  10240        // 128 rows * 80B
#define STAGE_BYTES 20480        // A tile + B tile
#define NSTAGE      3
#define SMEM_BYTES  61440        // 3 stages

// ---------------------------------------------------------------------------
// edge_index dtype detect + index load
// ---------------------------------------------------------------------------
__global__ void detect_kernel(const int* __restrict__ ei32) {
    __shared__ int any_nonzero;
    if (threadIdx.x == 0) any_nonzero = 0;
    __syncthreads();
    if (ei32[2 * threadIdx.x + 1] != 0) atomicOr(&any_nonzero, 1);
    __syncthreads();
    if (threadIdx.x == 0) g_is64 = (any_nonzero == 0) ? 1 : 0;
}
__device__ __forceinline__ int load_idx(const int* ei32, int pos) {
    int v = g_is64 ? ei32[2 * pos] : ei32[pos];
    return min(max(v, 0), NN_ - 1);
}

// ---------------------------------------------------------------------------
// CSR build: histogram -> scan (+ reset histogram) -> bucket fill
// ---------------------------------------------------------------------------
__global__ void icount_kernel(const int* __restrict__ ei32) {
    int e = blockIdx.x * 256 + threadIdx.x;
    if (e < EE_) atomicAdd(&g_icnt[load_idx(ei32, EE_ + e)], 1);
}

__global__ __launch_bounds__(1024) void scan_kernel() {
    __shared__ int buf[1024];
    __shared__ int carry;
    const int tid = threadIdx.x;
    if (tid == 0) carry = 0;
    __syncthreads();
    for (int chunk = 0; chunk < (NN_ + 1023) / 1024; chunk++) {
        int i = chunk * 1024 + tid;
        int v = (i < NN_) ? g_icnt[i] : 0;
        if (i < NN_) g_icnt[i] = 0;          // reset for next graph replay
        int add = carry;
        buf[tid] = v;
        __syncthreads();
        for (int off = 1; off < 1024; off <<= 1) {
            int t = (tid >= off) ? buf[tid - off] : 0;
            __syncthreads();
            buf[tid] += t;
            __syncthreads();
        }
        if (i < NN_) {
            int excl = add + buf[tid] - v;
            g_rowstart[i] = excl;
            g_pos[i] = excl;
        }
        __syncthreads();
        if (tid == 0) carry = add + buf[1023];
        __syncthreads();
    }
    if (tid == 0) g_rowstart[NN_] = carry;   // == EE_
}

__global__ void fill_kernel(const int* __restrict__ ei32) {
    int e = blockIdx.x * 256 + threadIdx.x;
    if (e < EE_) {
        int dst = load_idx(ei32, EE_ + e);
        int src = load_idx(ei32, e);
        int p = atomicAdd(&g_pos[dst], 1);
        g_ebkt[p] = e;
        g_esrc[p] = src;
    }
}

// ---------------------------------------------------------------------------
// fp32 -> fp16 convert (hi only)
// ---------------------------------------------------------------------------
__global__ void xcvt_kernel(const float* __restrict__ x) {
    size_t i4 = (size_t)blockIdx.x * 256 + threadIdx.x;   // 5.12M float4
    float4 v = ((const float4*)x)[i4];
    __half2 p0, p1;
    p0.x = __float2half_rn(v.x); p0.y = __float2half_rn(v.y);
    p1.x = __float2half_rn(v.z); p1.y = __float2half_rn(v.w);
    ((__half2*)g_xh)[i4 * 2 + 0] = p0;
    ((__half2*)g_xh)[i4 * 2 + 1] = p1;
}

__global__ void wprep_kernel(const float* __restrict__ W0,
                             const float* __restrict__ W1,
                             const float* __restrict__ W2) {
    const float* W = (blockIdx.y == 0) ? W0 : ((blockIdx.y == 1) ? W1 : W2);
    __half* H = (blockIdx.y == 0) ? g_WT0 : ((blockIdx.y == 1) ? g_WT2 : g_WT4);
    int k = blockIdx.x, n = threadIdx.x;
    H[n * CC_ + k] = __float2half_rn(W[k * CC_ + n]);
}

// ---------------------------------------------------------------------------
// Fused message gather, chunked-MLP version.
// Block = dst node. Per 32-edge chunk: stage eid/src/weights/edge_attr into
// shared (parallel), then per-channel loop issues independent g_xl row loads.
// ---------------------------------------------------------------------------
__global__ __launch_bounds__(256) void gather_kernel(
    const float* __restrict__ edge_attr,    // (E,16)
    const float* __restrict__ bond_W,       // (16,256)
    const float* __restrict__ bond_b,       // (256)
    const float* __restrict__ edge_weight)  // (RC, E)
{
    const int n = blockIdx.x;
    const int c = threadIdx.x;

    __shared__ int   s_eid[32];
    __shared__ int   s_src[32];
    __shared__ float s_w[4][32];
    __shared__ float s_ea[32][16];

    float bw[16];
#pragma unroll
    for (int d = 0; d < 16; d++) bw[d] = bond_W[d * CC_ + c];
    const float bb = bond_b[c];

    const int s0 = g_rowstart[n];
    const int s1 = g_rowstart[n + 1];
    const int deg = s1 - s0;

    float acc0 = 0.f, acc1 = 0.f, acc2 = 0.f, acc3 = 0.f;
    const size_t rs = (size_t)NN_ * CC_;

    for (int base = s0; base < s1; base += 32) {
        const int m = min(32, s1 - base);

        if (c < m) {
            int e = g_ebkt[base + c];
            s_eid[c] = e;
            s_src[c] = g_esrc[base + c];
            s_w[0][c] = __ldg(&edge_weight[0 * EE_ + e]);
            s_w[1][c] = __ldg(&edge_weight[1 * EE_ + e]);
            s_w[2][c] = __ldg(&edge_weight[2 * EE_ + e]);
            s_w[3][c] = __ldg(&edge_weight[3 * EE_ + e]);
        }
        __syncthreads();

        for (int j = c; j < m * 16; j += 256) {
            s_ea[j >> 4][j & 15] = __ldg(&edge_attr[s_eid[j >> 4] * 16 + (j & 15)]);
        }
        __syncthreads();

#pragma unroll 2
        for (int i = 0; i < m; i++) {
            float emb = bb;
#pragma unroll
            for (int d = 0; d < 16; d++) emb = fmaf(s_ea[i][d], bw[d], emb);

            const float* xr = g_xl + (size_t)s_src[i] * CC_ + c;
            float v0 = xr[0 * rs] + emb;
            float v1 = xr[1 * rs] + emb;
            float v2 = xr[2 * rs] + emb;
            float v3 = xr[3 * rs] + emb;
            const float k = 0.70710678118654752f;
            acc0 += 0.5f * v0 * (1.0f + erff(v0 * k)) * s_w[0][i];
            acc1 += 0.5f * v1 * (1.0f + erff(v1 * k)) * s_w[1][i];
            acc2 += 0.5f * v2 * (1.0f + erff(v2 * k)) * s_w[2][i];
            acc3 += 0.5f * v3 * (1.0f + erff(v3 * k)) * s_w[3][i];
        }
        __syncthreads();
    }

    const float s = 1.0f / (float)max(deg, 1);
    float a[4] = {acc0 * s, acc1 * s, acc2 * s, acc3 * s};
#pragma unroll
    for (int rc = 0; rc < RC_; rc++) {
        size_t off = (size_t)(rc * NN_ + n) * CC_ + c;
        g_ah[off] = __float2half_rn(a[rc]);
    }
}

// ---------------------------------------------------------------------------
// fp16 mma.sync GEMM, 3-stage cp.async pipeline (128x128 tile, 2 CTA/SM).
// 8 warps (2M x 4N), warp tile 64x32.
// which==0: g_xl = xh @ W0^T + lin_b            (K=256)
// which==1: out  = [ah,xh] @ [W2,W4]^T + linl_b (K=512)
// ---------------------------------------------------------------------------
__device__ __forceinline__ void load_stage(char* smem, int s, int tid,
                                           const __half* Ag, const __half* Bg) {
    uint32_t a32 = smem_u32(smem + s * STAGE_BYTES);
    uint32_t b32 = a32 + TILE_BYTES;
#pragma unroll
    for (int i = 0; i < 2; i++) {
        int idx = tid + i * 256;       // 0..511
        int r = idx >> 2, ch = idx & 3;
        cp16(a32 + r * ROWB + ch * 16,
             (const char*)Ag + ((size_t)r * CC_ + ch * 8) * 2);
    }
#pragma unroll
    for (int i = 0; i < 2; i++) {
        int idx = tid + i * 256;
        int r = idx >> 2, ch = idx & 3;
        cp16(b32 + r * ROWB + ch * 16,
             (const char*)Bg + ((size_t)r * CC_ + ch * 8) * 2);
    }
}

__global__ __launch_bounds__(256, 2) void mma_gemm(
    int which, const float* __restrict__ bias, float* __restrict__ out_ext)
{
    extern __shared__ __align__(128) char smem[];
    const int tid = threadIdx.x, lane = tid & 31, wid = tid >> 5;
    const int warp_m = wid & 1, warp_n = wid >> 1;
    const int bx = blockIdx.x, by = blockIdx.y;
    const int g = lane >> 3, lr = lane & 7;

    const __half *Aseg[2], *Bseg[2];
    int nseg;
    float* outp;
    if (which == 0) {
        Aseg[0] = g_xh;
        Bseg[0] = g_WT0;
        nseg = 1; outp = g_xl;
    } else {
        Aseg[0] = g_ah; Aseg[1] = g_xh;
        Bseg[0] = g_WT2; Bseg[1] = g_WT4;
        nseg = 2; outp = out_ext;
    }
    const int NC = nseg * 8;    // BK=32 chunks per 256-K segment

    float acc[4][4][4];
#pragma unroll
    for (int mt = 0; mt < 4; mt++)
#pragma unroll
        for (int nt = 0; nt < 4; nt++)
#pragma unroll
            for (int q = 0; q < 4; q++) acc[mt][nt][q] = 0.f;

    const size_t arow = (size_t)by * 128 * CC_;
    const size_t brow = (size_t)bx * 128 * CC_;

    load_stage(smem, 0, tid, Aseg[0] + arow, Bseg[0] + brow);
    CP_COMMIT();
    {
        int seg = 1 >> 3, ko = (1 & 7) * 32;
        load_stage(smem, 1, tid, Aseg[seg] + arow + ko, Bseg[seg] + brow + ko);
        CP_COMMIT();
    }

    int buf = 0;
    for (int c = 0; c < NC; c++) {
        if (c + 1 < NC) { CP_WAIT1(); } else { CP_WAIT0(); }
        __syncthreads();

        if (c + 2 < NC) {
            int seg = (c + 2) >> 3, ko = ((c + 2) & 7) * 32;
            int nb = (buf + 2 >= NSTAGE) ? buf + 2 - NSTAGE : buf + 2;
            load_stage(smem, nb, tid,
                       Aseg[seg] + arow + ko, Bseg[seg] + brow + ko);
            CP_COMMIT();
        }

        uint32_t a_base = smem_u32(smem + buf * STAGE_BYTES);
        uint32_t b_base = a_base + TILE_BYTES;
#pragma unroll
        for (int ks = 0; ks < 2; ks++) {
            uint32_t a[4][4];
#pragma unroll
            for (int mt = 0; mt < 4; mt++) {
                int row = warp_m * 64 + mt * 16 + (g & 1) * 8 + lr;
                LDSM4(a[mt], a_base + row * ROWB + ks * 32 + (g >> 1) * 16);
            }
            uint32_t b[2][4];
#pragma unroll
            for (int p = 0; p < 2; p++) {
                int row = warp_n * 32 + p * 16 + ((g >> 1) & 1) * 8 + lr;
                LDSM4(b[p], b_base + row * ROWB + ks * 32 + (g & 1) * 16);
            }
#pragma unroll
            for (int mt = 0; mt < 4; mt++)
#pragma unroll
                for (int nt = 0; nt < 4; nt++) {
                    int p = nt >> 1, h = (nt & 1) * 2;
                    MMA16816(acc[mt][nt], a[mt], b[p][h], b[p][h + 1]);
                }
        }
        buf = (buf + 1 >= NSTAGE) ? 0 : buf + 1;
    }

    const int tg = lane >> 2, tig = lane & 3;
#pragma unroll
    for (int mt = 0; mt < 4; mt++) {
#pragma unroll
        for (int nt = 0; nt < 4; nt++) {
            int row = by * 128 + warp_m * 64 + mt * 16 + tg;
            int col = bx * 128 + warp_n * 32 + nt * 8 + tig * 2;
            float b0 = bias[col], b1 = bias[col + 1];
            float2 v0, v1;
            v0.x = acc[mt][nt][0] + b0; v0.y = acc[mt][nt][1] + b1;
            v1.x = acc[mt][nt][2] + b0; v1.y = acc[mt][nt][3] + b1;
            *(float2*)(outp + (size_t)row * CC_ + col) = v0;
            *(float2*)(outp + (size_t)(row + 8) * CC_ + col) = v1;
        }
    }
}

// ---------------------------------------------------------------------------
extern "C" void kernel_launch(void* const* d_in, const int* in_sizes, int n_in,
                              void* d_out, int out_size) {
    const float* x           = (const float*)d_in[0];
    const float* edge_attr   = (const float*)d_in[1];
    const float* edge_weight = (const float*)d_in[2];
    const float* lin_W       = (const float*)d_in[3];
    const float* lin_b       = (const float*)d_in[4];
    const float* linl_W      = (const float*)d_in[5];
    const float* linl_b      = (const float*)d_in[6];
    const float* linr_W      = (const float*)d_in[7];
    const float* bond_W      = (const float*)d_in[8];
    const float* bond_b      = (const float*)d_in[9];
    const int*   edge_index  = (const int*)d_in[10];
    float*       out         = (float*)d_out;

    cudaFuncSetAttribute(mma_gemm, cudaFuncAttributeMaxDynamicSharedMemorySize,
                         SMEM_BYTES);

    // mma_gemm(0) in the 4th (profiled) slot.
    xcvt_kernel<<<20000, 256>>>(x);
    wprep_kernel<<<dim3(256, 3), 256>>>(lin_W, linl_W, linr_W);
    detect_kernel<<<1, 256>>>(edge_index);
    {
        dim3 grid(2, MTOT_ / 128);
        mma_gemm<<<grid, 256, SMEM_BYTES>>>(0, lin_b, nullptr);   // -> g_xl
    }
    icount_kernel<<<(EE_ + 255) / 256, 256>>>(edge_index);
    scan_kernel<<<1, 1024>>>();
    fill_kernel<<<(EE_ + 255) / 256, 256>>>(edge_index);
    gather_kernel<<<NN_, 256>>>(edge_attr, bond_W, bond_b, edge_weight);
    {
        dim3 grid(2, MTOT_ / 128);
        mma_gemm<<<grid, 256, SMEM_BYTES>>>(1, linl_b, out);      // -> out
    }
}